// round 3
// baseline (speedup 1.0000x reference)
#include <cuda_runtime.h>
#include <cstdint>

#define B_  4
#define N_  2048
#define C_  1024
#define H_  8
#define D_  128
#define TOK (B_ * N_)            // 8192 rows
#define BH  (B_ * H_)            // 32 batched heads
#define SCALE_ 0.08838834764831845f  // 128^-0.5
#define EPS_ 1e-5f

// ---------------- device scratch (allocation-free) ----------------
__device__ __align__(16) float g_h    [TOK * C_];        // LN output (reused for LN2)
__device__ __align__(16) float g_qkv  [TOK * 3 * C_];    // 96 MB
__device__ __align__(16) float g_q    [BH * N_ * D_];
__device__ __align__(16) float g_k    [BH * N_ * D_];
__device__ __align__(16) float g_v    [BH * N_ * D_];
__device__ __align__(16) float g_sc   [(size_t)BH * N_ * N_]; // 512 MB scores
__device__ __align__(16) float g_o    [BH * N_ * D_];
__device__ __align__(16) float g_ocat [TOK * C_];
__device__ __align__(16) float g_x1   [TOK * C_];        // after attn residual
__device__ __align__(16) float g_m1   [TOK * C_];
__device__ __align__(16) float g_bnscale[C_];
__device__ __align__(16) float g_bnshift[C_];

// ---------------- reductions ----------------
__device__ __forceinline__ float warpSum(float v) {
    #pragma unroll
    for (int o = 16; o > 0; o >>= 1) v += __shfl_xor_sync(0xffffffffu, v, o);
    return v;
}
__device__ __forceinline__ float warpMax(float v) {
    #pragma unroll
    for (int o = 16; o > 0; o >>= 1) v = fmaxf(v, __shfl_xor_sync(0xffffffffu, v, o));
    return v;
}

// ---------------- LayerNorm: one block per row, 256 threads, C=1024 ----------------
__global__ void __launch_bounds__(256) layernorm_kernel(
    const float* __restrict__ x, const float* __restrict__ g,
    const float* __restrict__ b, float* __restrict__ out)
{
    size_t row = blockIdx.x;
    int tid = threadIdx.x;
    const float4* xr = (const float4*)(x + row * C_);
    float4 v = xr[tid];
    float s  = v.x + v.y + v.z + v.w;
    float sq = v.x*v.x + v.y*v.y + v.z*v.z + v.w*v.w;

    __shared__ float red[2][8];
    float ws = warpSum(s), wq = warpSum(sq);
    int lane = tid & 31, wid = tid >> 5;
    if (lane == 0) { red[0][wid] = ws; red[1][wid] = wq; }
    __syncthreads();
    float tot = 0.f, totq = 0.f;
    #pragma unroll
    for (int i = 0; i < 8; ++i) { tot += red[0][i]; totq += red[1][i]; }
    float mean = tot * (1.f / C_);
    float var  = totq * (1.f / C_) - mean * mean;
    float rstd = rsqrtf(var + EPS_);

    float4 gg = ((const float4*)g)[tid];
    float4 bb = ((const float4*)b)[tid];
    float4 o4;
    o4.x = (v.x - mean) * rstd * gg.x + bb.x;
    o4.y = (v.y - mean) * rstd * gg.y + bb.y;
    o4.z = (v.z - mean) * rstd * gg.z + bb.z;
    o4.w = (v.w - mean) * rstd * gg.w + bb.w;
    ((float4*)(out + row * C_))[tid] = o4;
}

// ---------------- tiled SGEMM: C[m,n] = alpha * sum_k A[m,k] * B(k,n) ----------------
// TRANSB=true : B is [N,K] row-major (NT, "weight" layout)
// TRANSB=false: B is [K,N] row-major (NN)
// EPI: 0 none; 1 +bias+resid; 2 elu(+bias); 3 elu(+bias)*scale+shift+resid
#define BM 128
#define BN 128
#define BKK 8

template<int EPI, bool TRANSB>
__global__ void __launch_bounds__(256)
gemm_kernel(const float* __restrict__ A, const float* __restrict__ Bm,
            float* __restrict__ C, const float* __restrict__ resid,
            const float* __restrict__ bias, const float* __restrict__ scale,
            const float* __restrict__ shift,
            int M, int N, int K,
            long long sA, long long sB, long long sC, float alpha)
{
    __shared__ float As[BKK][BM];
    __shared__ float Bs[BKK][BN];

    int bz = blockIdx.z;
    A  += sA * bz;
    Bm += sB * bz;
    C  += sC * bz;
    const float* R = resid ? resid + sC * bz : nullptr;

    int tid = threadIdx.x;
    int tx = tid & 15, ty = tid >> 4;
    int mBase = blockIdx.y * BM;
    int nBase = blockIdx.x * BN;

    int aRow = tid >> 1;
    int aCol = (tid & 1) * 4;
    int bRowNN = tid >> 5;           // 0..7
    int bColNN = (tid & 31) * 4;     // 0..124

    float acc[8][8];
    #pragma unroll
    for (int i = 0; i < 8; ++i)
        #pragma unroll
        for (int j = 0; j < 8; ++j) acc[i][j] = 0.f;

    for (int k0 = 0; k0 < K; k0 += BKK) {
        float4 av = *(const float4*)&A[(size_t)(mBase + aRow) * K + k0 + aCol];
        As[aCol + 0][aRow] = av.x;
        As[aCol + 1][aRow] = av.y;
        As[aCol + 2][aRow] = av.z;
        As[aCol + 3][aRow] = av.w;
        if (TRANSB) {
            float4 bv = *(const float4*)&Bm[(size_t)(nBase + aRow) * K + k0 + aCol];
            Bs[aCol + 0][aRow] = bv.x;
            Bs[aCol + 1][aRow] = bv.y;
            Bs[aCol + 2][aRow] = bv.z;
            Bs[aCol + 3][aRow] = bv.w;
        } else {
            float4 bv = *(const float4*)&Bm[(size_t)(k0 + bRowNN) * N + nBase + bColNN];
            *(float4*)&Bs[bRowNN][bColNN] = bv;
        }
        __syncthreads();
        #pragma unroll
        for (int k = 0; k < BKK; ++k) {
            float4 a0 = *(const float4*)&As[k][ty * 8];
            float4 a1 = *(const float4*)&As[k][ty * 8 + 4];
            float4 b0 = *(const float4*)&Bs[k][tx * 8];
            float4 b1 = *(const float4*)&Bs[k][tx * 8 + 4];
            float ar[8] = {a0.x, a0.y, a0.z, a0.w, a1.x, a1.y, a1.z, a1.w};
            float br[8] = {b0.x, b0.y, b0.z, b0.w, b1.x, b1.y, b1.z, b1.w};
            #pragma unroll
            for (int i = 0; i < 8; ++i)
                #pragma unroll
                for (int j = 0; j < 8; ++j)
                    acc[i][j] = fmaf(ar[i], br[j], acc[i][j]);
        }
        __syncthreads();
    }

    #pragma unroll
    for (int i = 0; i < 8; ++i) {
        int m = mBase + ty * 8 + i;
        #pragma unroll
        for (int j = 0; j < 8; ++j) {
            int n = nBase + tx * 8 + j;
            size_t idx = (size_t)m * N + n;
            float v = acc[i][j] * alpha;
            if (EPI == 1) {
                v = v + bias[n] + R[idx];
            } else if (EPI == 2) {
                v += bias[n];
                v = v > 0.f ? v : expm1f(v);
            } else if (EPI == 3) {
                v += bias[n];
                v = v > 0.f ? v : expm1f(v);
                v = v * scale[n] + shift[n] + R[idx];
            }
            C[idx] = v;
        }
    }
}

// ---------------- row softmax over L=2048, one block per row ----------------
__global__ void __launch_bounds__(256) softmax_kernel(float* __restrict__ s)
{
    size_t row = blockIdx.x;
    float* r = s + row * (size_t)N_;
    int tid = threadIdx.x;

    float vals[8];
    float lmax = -3.4e38f;
    #pragma unroll
    for (int i = 0; i < 8; ++i) {
        vals[i] = r[tid + i * 256];
        lmax = fmaxf(lmax, vals[i]);
    }
    __shared__ float red[8];
    float wm = warpMax(lmax);
    int lane = tid & 31, wid = tid >> 5;
    if (lane == 0) red[wid] = wm;
    __syncthreads();
    float gmax = -3.4e38f;
    #pragma unroll
    for (int i = 0; i < 8; ++i) gmax = fmaxf(gmax, red[i]);
    __syncthreads();

    float lsum = 0.f;
    #pragma unroll
    for (int i = 0; i < 8; ++i) {
        vals[i] = expf(vals[i] - gmax);
        lsum += vals[i];
    }
    float ws = warpSum(lsum);
    if (lane == 0) red[wid] = ws;
    __syncthreads();
    float gsum = 0.f;
    #pragma unroll
    for (int i = 0; i < 8; ++i) gsum += red[i];
    float inv = 1.f / gsum;
    #pragma unroll
    for (int i = 0; i < 8; ++i) r[tid + i * 256] = vals[i] * inv;
}

// ---------------- qkv [B,N,3,H,D] -> q,k,v [BH,N,D] ----------------
__global__ void __launch_bounds__(256) split_qkv_kernel(
    const float* __restrict__ qkv, float* __restrict__ q,
    float* __restrict__ k, float* __restrict__ v)
{
    int idx = blockIdx.x * 256 + threadIdx.x;   // over BH*N*D = 8388608
    int d = idx & (D_ - 1);
    int n = (idx >> 7) & (N_ - 1);
    int h = (idx >> 18) & (H_ - 1);
    int b = idx >> 21;
    size_t src = (size_t)(b * N_ + n) * (3 * C_) + h * D_ + d;
    q[idx] = qkv[src];
    k[idx] = qkv[src + C_];
    v[idx] = qkv[src + 2 * C_];
}

// ---------------- o [BH,N,D] -> [B,N,C] ----------------
__global__ void __launch_bounds__(256) merge_o_kernel(
    const float* __restrict__ o, float* __restrict__ ocat)
{
    int idx = blockIdx.x * 256 + threadIdx.x;
    int d = idx & (D_ - 1);
    int n = (idx >> 7) & (N_ - 1);
    int h = (idx >> 18) & (H_ - 1);
    int b = idx >> 21;
    ocat[(size_t)(b * N_ + n) * C_ + h * D_ + d] = o[idx];
}

// ---------------- BatchNorm fold ----------------
__global__ void bn_prep_kernel(const float* __restrict__ g, const float* __restrict__ b,
                               const float* __restrict__ mean, const float* __restrict__ var,
                               float* __restrict__ sc, float* __restrict__ sh)
{
    int i = blockIdx.x * 256 + threadIdx.x;
    if (i < C_) {
        float s = g[i] * rsqrtf(var[i] + EPS_);
        sc[i] = s;
        sh[i] = b[i] - mean[i] * s;
    }
}

// ---------------- host ----------------
static float* sym(const void* s) {
    void* p = nullptr;
    cudaGetSymbolAddress(&p, s);
    return (float*)p;
}

extern "C" void kernel_launch(void* const* d_in, const int* in_sizes, int n_in,
                              void* d_out, int out_size)
{
    const float* x      = (const float*)d_in[0];
    const float* ln1_g  = (const float*)d_in[1];
    const float* ln1_b  = (const float*)d_in[2];
    const float* w_qkv  = (const float*)d_in[3];
    const float* w_proj = (const float*)d_in[4];
    const float* b_proj = (const float*)d_in[5];
    const float* ln2_g  = (const float*)d_in[6];
    const float* ln2_b  = (const float*)d_in[7];
    const float* w1     = (const float*)d_in[8];
    const float* b1     = (const float*)d_in[9];
    const float* w2     = (const float*)d_in[10];
    const float* b2     = (const float*)d_in[11];
    const float* bn_g   = (const float*)d_in[12];
    const float* bn_b   = (const float*)d_in[13];
    const float* bn_m   = (const float*)d_in[14];
    const float* bn_v   = (const float*)d_in[15];
    float* out = (float*)d_out;

    float* h    = sym(g_h);
    float* qkv  = sym(g_qkv);
    float* q    = sym(g_q);
    float* k    = sym(g_k);
    float* v    = sym(g_v);
    float* sc   = sym(g_sc);
    float* o    = sym(g_o);
    float* ocat = sym(g_ocat);
    float* x1   = sym(g_x1);
    float* m1   = sym(g_m1);
    float* bns  = sym(g_bnscale);
    float* bnh  = sym(g_bnshift);

    const int elemBlocks = (BH * N_ * D_) / 256;

    // 1) LN1
    layernorm_kernel<<<TOK, 256>>>(x, ln1_g, ln1_b, h);

    // 2) qkv = h @ Wqkv^T   [8192,1024]x[3072,1024]^T
    gemm_kernel<0, true><<<dim3(3 * C_ / BN, TOK / BM, 1), 256>>>(
        h, w_qkv, qkv, nullptr, nullptr, nullptr, nullptr,
        TOK, 3 * C_, C_, 0, 0, 0, 1.f);

    // 3) split heads
    split_qkv_kernel<<<elemBlocks, 256>>>(qkv, q, k, v);

    // 4) scores = q @ k^T * SCALE  (batched over 32 heads)
    gemm_kernel<0, true><<<dim3(N_ / BN, N_ / BM, BH), 256>>>(
        q, k, sc, nullptr, nullptr, nullptr, nullptr,
        N_, N_, D_, (long long)N_ * D_, (long long)N_ * D_, (long long)N_ * N_, SCALE_);

    // 5) softmax rows
    softmax_kernel<<<BH * N_, 256>>>(sc);

    // 6) o = P @ V  (batched NN)
    gemm_kernel<0, false><<<dim3(D_ / BN, N_ / BM, BH), 256>>>(
        sc, v, o, nullptr, nullptr, nullptr, nullptr,
        N_, D_, N_, (long long)N_ * N_, (long long)N_ * D_, (long long)N_ * D_, 1.f);

    // 7) merge heads
    merge_o_kernel<<<elemBlocks, 256>>>(o, ocat);

    // 8) x1 = ocat @ Wproj^T + b_proj + x
    gemm_kernel<1, true><<<dim3(C_ / BN, TOK / BM, 1), 256>>>(
        ocat, w_proj, x1, x, b_proj, nullptr, nullptr,
        TOK, C_, C_, 0, 0, 0, 1.f);

    // 9) LN2
    layernorm_kernel<<<TOK, 256>>>(x1, ln2_g, ln2_b, h);

    // 10) m1 = elu(h @ W1^T + b1)
    gemm_kernel<2, true><<<dim3(C_ / BN, TOK / BM, 1), 256>>>(
        h, w1, m1, nullptr, b1, nullptr, nullptr,
        TOK, C_, C_, 0, 0, 0, 1.f);

    // 11) BN fold
    bn_prep_kernel<<<4, 256>>>(bn_g, bn_b, bn_m, bn_v, bns, bnh);

    // 12) out = bn(elu(m1 @ W2^T + b2)) + x1
    gemm_kernel<3, true><<<dim3(C_ / BN, TOK / BM, 1), 256>>>(
        m1, w2, out, x1, b2, bns, bnh,
        TOK, C_, C_, 0, 0, 0, 1.f);

    (void)in_sizes; (void)n_in; (void)out_size;
}

// round 4
// speedup vs baseline: 2.0529x; 2.0529x over previous
#include <cuda_runtime.h>
#include <cstdint>

#define B_  4
#define N_  2048
#define C_  1024
#define H_  8
#define D_  128
#define TOK (B_ * N_)            // 8192 rows
#define BH  (B_ * H_)            // 32 batched heads
#define SCALE_ 0.08838834764831845f  // 128^-0.5
#define EPS_ 1e-5f

// ---------------- device scratch (allocation-free) ----------------
__device__ __align__(16) float g_h    [TOK * C_];
__device__ __align__(16) float g_qkv  [TOK * 3 * C_];
__device__ __align__(16) float g_q    [BH * N_ * D_];
__device__ __align__(16) float g_k    [BH * N_ * D_];
__device__ __align__(16) float g_v    [BH * N_ * D_];
__device__ __align__(16) float g_sc   [(size_t)BH * N_ * N_]; // 512 MB scores
__device__ __align__(16) float g_o    [BH * N_ * D_];
__device__ __align__(16) float g_ocat [TOK * C_];
__device__ __align__(16) float g_x1   [TOK * C_];
__device__ __align__(16) float g_m1   [TOK * C_];
__device__ __align__(16) float g_bnscale[C_];
__device__ __align__(16) float g_bnshift[C_];

// ---------------- helpers ----------------
__device__ __forceinline__ float warpSum(float v) {
    #pragma unroll
    for (int o = 16; o > 0; o >>= 1) v += __shfl_xor_sync(0xffffffffu, v, o);
    return v;
}
__device__ __forceinline__ float warpMax(float v) {
    #pragma unroll
    for (int o = 16; o > 0; o >>= 1) v = fmaxf(v, __shfl_xor_sync(0xffffffffu, v, o));
    return v;
}
__device__ __forceinline__ uint32_t f2tf32(float x) {
    uint32_t r;
    asm("cvt.rna.tf32.f32 %0, %1;" : "=r"(r) : "f"(x));
    return r;
}
__device__ __forceinline__ void mma_tf32(float* c, const uint32_t* a, const uint32_t* b) {
    asm volatile(
        "mma.sync.aligned.m16n8k8.row.col.f32.tf32.tf32.f32 "
        "{%0,%1,%2,%3}, {%4,%5,%6,%7}, {%8,%9}, {%0,%1,%2,%3};\n"
        : "+f"(c[0]), "+f"(c[1]), "+f"(c[2]), "+f"(c[3])
        : "r"(a[0]), "r"(a[1]), "r"(a[2]), "r"(a[3]), "r"(b[0]), "r"(b[1]));
}

// ---------------- LayerNorm ----------------
__global__ void __launch_bounds__(256) layernorm_kernel(
    const float* __restrict__ x, const float* __restrict__ g,
    const float* __restrict__ b, float* __restrict__ out)
{
    size_t row = blockIdx.x;
    int tid = threadIdx.x;
    const float4* xr = (const float4*)(x + row * C_);
    float4 v = xr[tid];
    float s  = v.x + v.y + v.z + v.w;
    float sq = v.x*v.x + v.y*v.y + v.z*v.z + v.w*v.w;

    __shared__ float red[2][8];
    float ws = warpSum(s), wq = warpSum(sq);
    int lane = tid & 31, wid = tid >> 5;
    if (lane == 0) { red[0][wid] = ws; red[1][wid] = wq; }
    __syncthreads();
    float tot = 0.f, totq = 0.f;
    #pragma unroll
    for (int i = 0; i < 8; ++i) { tot += red[0][i]; totq += red[1][i]; }
    float mean = tot * (1.f / C_);
    float var  = totq * (1.f / C_) - mean * mean;
    float rstd = rsqrtf(var + EPS_);

    float4 gg = ((const float4*)g)[tid];
    float4 bb = ((const float4*)b)[tid];
    float4 o4;
    o4.x = (v.x - mean) * rstd * gg.x + bb.x;
    o4.y = (v.y - mean) * rstd * gg.y + bb.y;
    o4.z = (v.z - mean) * rstd * gg.z + bb.z;
    o4.w = (v.w - mean) * rstd * gg.w + bb.w;
    ((float4*)(out + row * C_))[tid] = o4;
}

// ---------------- TF32 tensor-core GEMM ----------------
// C[m,n] = alpha * sum_k A[m,k] * B(k,n)
// TRANSB=true : B is [N,K] row-major (weight layout);  false: B is [K,N]
// EPI: 0 none; 1 +bias+resid; 2 elu(+bias); 3 elu(+bias)*scale+shift+resid
#define BM 128
#define BN 128
#define BK 16

template<int EPI, bool TRANSB>
__global__ void __launch_bounds__(256)
gemm_tc(const float* __restrict__ A, const float* __restrict__ Bm,
        float* __restrict__ C, const float* __restrict__ resid,
        const float* __restrict__ bias, const float* __restrict__ scale,
        const float* __restrict__ shift,
        int M, int N, int K,
        long long sA, long long sB, long long sC, float alpha)
{
    __shared__ uint32_t As[2][BK][BM + 4];
    __shared__ uint32_t Bs[2][BK][BN + 4];

    int bz = blockIdx.z;
    A  += sA * bz;  Bm += sB * bz;  C  += sC * bz;
    const float* R = resid ? resid + sC * bz : nullptr;

    int tid  = threadIdx.x;
    int lane = tid & 31, warpId = tid >> 5;
    int grp  = lane >> 2, tig = lane & 3;
    int wm   = (warpId & 3) * 32;   // 4 warps along M
    int wn   = (warpId >> 2) * 64;  // 2 warps along N
    int mBase = blockIdx.y * BM;
    int nBase = blockIdx.x * BN;

    // global-load indices
    int lRow = tid >> 1;            // 0..127  (row of A / row of B^T)
    int lCol = (tid & 1) * 8;       // k offset 0 or 8
    int nnK  = tid >> 4;            // 0..15   (NN-B k row)
    int nnN  = (tid & 15) * 8;      // 0..120  (NN-B n col)

    float acc[2][8][4];
    #pragma unroll
    for (int mi = 0; mi < 2; ++mi)
        #pragma unroll
        for (int ni = 0; ni < 8; ++ni)
            #pragma unroll
            for (int e = 0; e < 4; ++e) acc[mi][ni][e] = 0.f;

    float aReg[8], bReg[8];
    int nk = K / BK;

    // ---- prologue: load tile 0 ----
    {
        const float4 a0 = *(const float4*)&A[(size_t)(mBase + lRow) * K + lCol];
        const float4 a1 = *(const float4*)&A[(size_t)(mBase + lRow) * K + lCol + 4];
        aReg[0]=a0.x; aReg[1]=a0.y; aReg[2]=a0.z; aReg[3]=a0.w;
        aReg[4]=a1.x; aReg[5]=a1.y; aReg[6]=a1.z; aReg[7]=a1.w;
        if (TRANSB) {
            const float4 b0 = *(const float4*)&Bm[(size_t)(nBase + lRow) * K + lCol];
            const float4 b1 = *(const float4*)&Bm[(size_t)(nBase + lRow) * K + lCol + 4];
            bReg[0]=b0.x; bReg[1]=b0.y; bReg[2]=b0.z; bReg[3]=b0.w;
            bReg[4]=b1.x; bReg[5]=b1.y; bReg[6]=b1.z; bReg[7]=b1.w;
        } else {
            const float4 b0 = *(const float4*)&Bm[(size_t)nnK * N + nBase + nnN];
            const float4 b1 = *(const float4*)&Bm[(size_t)nnK * N + nBase + nnN + 4];
            bReg[0]=b0.x; bReg[1]=b0.y; bReg[2]=b0.z; bReg[3]=b0.w;
            bReg[4]=b1.x; bReg[5]=b1.y; bReg[6]=b1.z; bReg[7]=b1.w;
        }
        #pragma unroll
        for (int j = 0; j < 8; ++j) As[0][lCol + j][lRow] = f2tf32(aReg[j]);
        if (TRANSB) {
            #pragma unroll
            for (int j = 0; j < 8; ++j) Bs[0][lCol + j][lRow] = f2tf32(bReg[j]);
        } else {
            #pragma unroll
            for (int j = 0; j < 8; ++j) Bs[0][nnK][nnN + j] = f2tf32(bReg[j]);
        }
    }

    for (int it = 0; it < nk; ++it) {
        __syncthreads();
        int buf = it & 1;
        bool more = (it + 1 < nk);
        if (more) {
            int k0 = (it + 1) * BK;
            const float4 a0 = *(const float4*)&A[(size_t)(mBase + lRow) * K + k0 + lCol];
            const float4 a1 = *(const float4*)&A[(size_t)(mBase + lRow) * K + k0 + lCol + 4];
            aReg[0]=a0.x; aReg[1]=a0.y; aReg[2]=a0.z; aReg[3]=a0.w;
            aReg[4]=a1.x; aReg[5]=a1.y; aReg[6]=a1.z; aReg[7]=a1.w;
            if (TRANSB) {
                const float4 b0 = *(const float4*)&Bm[(size_t)(nBase + lRow) * K + k0 + lCol];
                const float4 b1 = *(const float4*)&Bm[(size_t)(nBase + lRow) * K + k0 + lCol + 4];
                bReg[0]=b0.x; bReg[1]=b0.y; bReg[2]=b0.z; bReg[3]=b0.w;
                bReg[4]=b1.x; bReg[5]=b1.y; bReg[6]=b1.z; bReg[7]=b1.w;
            } else {
                const float4 b0 = *(const float4*)&Bm[(size_t)(k0 + nnK) * N + nBase + nnN];
                const float4 b1 = *(const float4*)&Bm[(size_t)(k0 + nnK) * N + nBase + nnN + 4];
                bReg[0]=b0.x; bReg[1]=b0.y; bReg[2]=b0.z; bReg[3]=b0.w;
                bReg[4]=b1.x; bReg[5]=b1.y; bReg[6]=b1.z; bReg[7]=b1.w;
            }
        }

        // ---- compute from smem[buf] ----
        #pragma unroll
        for (int kk = 0; kk < BK; kk += 8) {
            uint32_t af[2][4];
            #pragma unroll
            for (int mi = 0; mi < 2; ++mi) {
                int m = wm + mi * 16 + grp;
                af[mi][0] = As[buf][kk + tig    ][m];
                af[mi][1] = As[buf][kk + tig    ][m + 8];
                af[mi][2] = As[buf][kk + tig + 4][m];
                af[mi][3] = As[buf][kk + tig + 4][m + 8];
            }
            uint32_t bf[8][2];
            #pragma unroll
            for (int ni = 0; ni < 8; ++ni) {
                int n = wn + ni * 8 + grp;
                bf[ni][0] = Bs[buf][kk + tig    ][n];
                bf[ni][1] = Bs[buf][kk + tig + 4][n];
            }
            #pragma unroll
            for (int mi = 0; mi < 2; ++mi)
                #pragma unroll
                for (int ni = 0; ni < 8; ++ni)
                    mma_tf32(acc[mi][ni], af[mi], bf[ni]);
        }

        if (more) {
            int nbuf = buf ^ 1;
            #pragma unroll
            for (int j = 0; j < 8; ++j) As[nbuf][lCol + j][lRow] = f2tf32(aReg[j]);
            if (TRANSB) {
                #pragma unroll
                for (int j = 0; j < 8; ++j) Bs[nbuf][lCol + j][lRow] = f2tf32(bReg[j]);
            } else {
                #pragma unroll
                for (int j = 0; j < 8; ++j) Bs[nbuf][nnK][nnN + j] = f2tf32(bReg[j]);
            }
        }
    }

    // ---- epilogue ----
    #pragma unroll
    for (int mi = 0; mi < 2; ++mi) {
        #pragma unroll
        for (int ni = 0; ni < 8; ++ni) {
            int c0 = nBase + wn + ni * 8 + tig * 2;
            #pragma unroll
            for (int p = 0; p < 2; ++p) {
                int r = mBase + wm + mi * 16 + grp + p * 8;
                size_t idx = (size_t)r * N + c0;
                float v0 = acc[mi][ni][p * 2 + 0] * alpha;
                float v1 = acc[mi][ni][p * 2 + 1] * alpha;
                if (EPI == 1) {
                    v0 += bias[c0]     + R[idx];
                    v1 += bias[c0 + 1] + R[idx + 1];
                } else if (EPI == 2) {
                    v0 += bias[c0];     v0 = v0 > 0.f ? v0 : expm1f(v0);
                    v1 += bias[c0 + 1]; v1 = v1 > 0.f ? v1 : expm1f(v1);
                } else if (EPI == 3) {
                    v0 += bias[c0];     v0 = v0 > 0.f ? v0 : expm1f(v0);
                    v1 += bias[c0 + 1]; v1 = v1 > 0.f ? v1 : expm1f(v1);
                    v0 = v0 * scale[c0]     + shift[c0]     + R[idx];
                    v1 = v1 * scale[c0 + 1] + shift[c0 + 1] + R[idx + 1];
                }
                float2 o2 = make_float2(v0, v1);
                *(float2*)&C[idx] = o2;
            }
        }
    }
}

// ---------------- row softmax over 2048 ----------------
__global__ void __launch_bounds__(256) softmax_kernel(float* __restrict__ s)
{
    size_t row = blockIdx.x;
    float* r = s + row * (size_t)N_;
    int tid = threadIdx.x;

    float vals[8];
    float lmax = -3.4e38f;
    #pragma unroll
    for (int i = 0; i < 8; ++i) {
        vals[i] = r[tid + i * 256];
        lmax = fmaxf(lmax, vals[i]);
    }
    __shared__ float red[8];
    float wm = warpMax(lmax);
    int lane = tid & 31, wid = tid >> 5;
    if (lane == 0) red[wid] = wm;
    __syncthreads();
    float gmax = -3.4e38f;
    #pragma unroll
    for (int i = 0; i < 8; ++i) gmax = fmaxf(gmax, red[i]);
    __syncthreads();

    float lsum = 0.f;
    #pragma unroll
    for (int i = 0; i < 8; ++i) {
        vals[i] = expf(vals[i] - gmax);
        lsum += vals[i];
    }
    float ws = warpSum(lsum);
    if (lane == 0) red[wid] = ws;
    __syncthreads();
    float gsum = 0.f;
    #pragma unroll
    for (int i = 0; i < 8; ++i) gsum += red[i];
    float inv = 1.f / gsum;
    #pragma unroll
    for (int i = 0; i < 8; ++i) r[tid + i * 256] = vals[i] * inv;
}

// ---------------- qkv [B,N,3,H,D] -> q,k,v [BH,N,D] ----------------
__global__ void __launch_bounds__(256) split_qkv_kernel(
    const float* __restrict__ qkv, float* __restrict__ q,
    float* __restrict__ k, float* __restrict__ v)
{
    int idx = blockIdx.x * 256 + threadIdx.x;
    int d = idx & (D_ - 1);
    int n = (idx >> 7) & (N_ - 1);
    int h = (idx >> 18) & (H_ - 1);
    int b = idx >> 21;
    size_t src = (size_t)(b * N_ + n) * (3 * C_) + h * D_ + d;
    q[idx] = qkv[src];
    k[idx] = qkv[src + C_];
    v[idx] = qkv[src + 2 * C_];
}

// ---------------- o [BH,N,D] -> [B,N,C] ----------------
__global__ void __launch_bounds__(256) merge_o_kernel(
    const float* __restrict__ o, float* __restrict__ ocat)
{
    int idx = blockIdx.x * 256 + threadIdx.x;
    int d = idx & (D_ - 1);
    int n = (idx >> 7) & (N_ - 1);
    int h = (idx >> 18) & (H_ - 1);
    int b = idx >> 21;
    ocat[(size_t)(b * N_ + n) * C_ + h * D_ + d] = o[idx];
}

// ---------------- BatchNorm fold ----------------
__global__ void bn_prep_kernel(const float* __restrict__ g, const float* __restrict__ b,
                               const float* __restrict__ mean, const float* __restrict__ var,
                               float* __restrict__ sc, float* __restrict__ sh)
{
    int i = blockIdx.x * 256 + threadIdx.x;
    if (i < C_) {
        float s = g[i] * rsqrtf(var[i] + EPS_);
        sc[i] = s;
        sh[i] = b[i] - mean[i] * s;
    }
}

// ---------------- host ----------------
static float* sym(const void* s) {
    void* p = nullptr;
    cudaGetSymbolAddress(&p, s);
    return (float*)p;
}

extern "C" void kernel_launch(void* const* d_in, const int* in_sizes, int n_in,
                              void* d_out, int out_size)
{
    const float* x      = (const float*)d_in[0];
    const float* ln1_g  = (const float*)d_in[1];
    const float* ln1_b  = (const float*)d_in[2];
    const float* w_qkv  = (const float*)d_in[3];
    const float* w_proj = (const float*)d_in[4];
    const float* b_proj = (const float*)d_in[5];
    const float* ln2_g  = (const float*)d_in[6];
    const float* ln2_b  = (const float*)d_in[7];
    const float* w1     = (const float*)d_in[8];
    const float* b1     = (const float*)d_in[9];
    const float* w2     = (const float*)d_in[10];
    const float* b2     = (const float*)d_in[11];
    const float* bn_g   = (const float*)d_in[12];
    const float* bn_b   = (const float*)d_in[13];
    const float* bn_m   = (const float*)d_in[14];
    const float* bn_v   = (const float*)d_in[15];
    float* out = (float*)d_out;

    float* h    = sym(g_h);
    float* qkv  = sym(g_qkv);
    float* q    = sym(g_q);
    float* k    = sym(g_k);
    float* v    = sym(g_v);
    float* sc   = sym(g_sc);
    float* o    = sym(g_o);
    float* ocat = sym(g_ocat);
    float* x1   = sym(g_x1);
    float* m1   = sym(g_m1);
    float* bns  = sym(g_bnscale);
    float* bnh  = sym(g_bnshift);

    const int elemBlocks = (BH * N_ * D_) / 256;

    // 1) LN1
    layernorm_kernel<<<TOK, 256>>>(x, ln1_g, ln1_b, h);

    // 2) qkv = h @ Wqkv^T
    gemm_tc<0, true><<<dim3(3 * C_ / BN, TOK / BM, 1), 256>>>(
        h, w_qkv, qkv, nullptr, nullptr, nullptr, nullptr,
        TOK, 3 * C_, C_, 0, 0, 0, 1.f);

    // 3) split heads
    split_qkv_kernel<<<elemBlocks, 256>>>(qkv, q, k, v);

    // 4) scores = q @ k^T * SCALE
    gemm_tc<0, true><<<dim3(N_ / BN, N_ / BM, BH), 256>>>(
        q, k, sc, nullptr, nullptr, nullptr, nullptr,
        N_, N_, D_, (long long)N_ * D_, (long long)N_ * D_, (long long)N_ * N_, SCALE_);

    // 5) softmax
    softmax_kernel<<<BH * N_, 256>>>(sc);

    // 6) o = P @ V
    gemm_tc<0, false><<<dim3(D_ / BN, N_ / BM, BH), 256>>>(
        sc, v, o, nullptr, nullptr, nullptr, nullptr,
        N_, D_, N_, (long long)N_ * N_, (long long)N_ * D_, (long long)N_ * D_, 1.f);

    // 7) merge heads
    merge_o_kernel<<<elemBlocks, 256>>>(o, ocat);

    // 8) x1 = ocat @ Wproj^T + b_proj + x
    gemm_tc<1, true><<<dim3(C_ / BN, TOK / BM, 1), 256>>>(
        ocat, w_proj, x1, x, b_proj, nullptr, nullptr,
        TOK, C_, C_, 0, 0, 0, 1.f);

    // 9) LN2
    layernorm_kernel<<<TOK, 256>>>(x1, ln2_g, ln2_b, h);

    // 10) m1 = elu(h @ W1^T + b1)
    gemm_tc<2, true><<<dim3(C_ / BN, TOK / BM, 1), 256>>>(
        h, w1, m1, nullptr, b1, nullptr, nullptr,
        TOK, C_, C_, 0, 0, 0, 1.f);

    // 11) BN fold
    bn_prep_kernel<<<4, 256>>>(bn_g, bn_b, bn_m, bn_v, bns, bnh);

    // 12) out = bn(elu(m1 @ W2^T + b2)) + x1
    gemm_tc<3, true><<<dim3(C_ / BN, TOK / BM, 1), 256>>>(
        m1, w2, out, x1, b2, bns, bnh,
        TOK, C_, C_, 0, 0, 0, 1.f);

    (void)in_sizes; (void)n_in; (void)out_size;
}